// round 4
// baseline (speedup 1.0000x reference)
#include <cuda_runtime.h>
#include <cuda_bf16.h>
#include <cstdint>

#define NX 16384
#define NS 4096
#define DD 256

#define TM 256              // CTA tile M
#define TN 128              // CTA tile N
#define MTILES (NX / TM)    // 64
#define NTILES_TOT ((NX / TM) * (NS / TN))  // 2048
#define BK 64               // K per stage (64 bf16 = 128B rows)
#define A_STAGE (TM * 128)  // 32 KB
#define B_STAGE (TN * 128)  // 16 KB
#define STAGE (A_STAGE + B_STAGE)  // 48 KB
#define DYN_SMEM (3 * STAGE)       // 147456

// Scratch (device globals; no allocation allowed)
__device__ __align__(16) __nv_bfloat16 g_xbf[NX * DD];
__device__ __align__(16) __nv_bfloat16 g_sbf[NS * DD];
__device__ float g_xsq[NX];
__device__ float g_ssq[NS];

// ---------------------------------------------------------------------------
// Prep: fp32 -> bf16 + row squared norms. One warp per row, 8 floats/lane.
// ---------------------------------------------------------------------------
__global__ void prep_kernel(const float* __restrict__ x,
                            const float* __restrict__ s) {
    int warp = (blockIdx.x * blockDim.x + threadIdx.x) >> 5;
    int lane = threadIdx.x & 31;
    if (warp >= NX + NS) return;
    const float* src;
    __nv_bfloat16* dst;
    float* sqout;
    if (warp < NX) {
        src = x + (size_t)warp * DD; dst = g_xbf + (size_t)warp * DD; sqout = g_xsq + warp;
    } else {
        int r = warp - NX;
        src = s + (size_t)r * DD; dst = g_sbf + (size_t)r * DD; sqout = g_ssq + r;
    }
    float4 v0 = reinterpret_cast<const float4*>(src)[lane * 2];
    float4 v1 = reinterpret_cast<const float4*>(src)[lane * 2 + 1];
    __nv_bfloat162 p0 = __floats2bfloat162_rn(v0.x, v0.y);
    __nv_bfloat162 p1 = __floats2bfloat162_rn(v0.z, v0.w);
    __nv_bfloat162 p2 = __floats2bfloat162_rn(v1.x, v1.y);
    __nv_bfloat162 p3 = __floats2bfloat162_rn(v1.z, v1.w);
    uint4 pk;
    pk.x = *reinterpret_cast<uint32_t*>(&p0);
    pk.y = *reinterpret_cast<uint32_t*>(&p1);
    pk.z = *reinterpret_cast<uint32_t*>(&p2);
    pk.w = *reinterpret_cast<uint32_t*>(&p3);
    reinterpret_cast<uint4*>(dst)[lane] = pk;
    float p = v0.x * v0.x + v0.y * v0.y + v0.z * v0.z + v0.w * v0.w +
              v1.x * v1.x + v1.y * v1.y + v1.z * v1.z + v1.w * v1.w;
#pragma unroll
    for (int o = 16; o; o >>= 1) p += __shfl_xor_sync(0xffffffffu, p, o);
    if (lane == 0) *sqout = p;
}

// ---------------------------------------------------------------------------
// Persistent HMMA GEMM + RBF epilogue.
// CTA 256x128, 8 warps (4Mx2N grid of 64x64 warp tiles), BK=64, 3-stage
// cp.async stream continuous across tiles (epilogue overlaps next-tile loads).
// SMEM: 128B rows, XOR-16B swizzle -> conflict-free stores AND ldmatrix.
// ---------------------------------------------------------------------------
__device__ __forceinline__ uint32_t cvta_s(const void* p) {
    uint32_t a;
    asm("{ .reg .u64 t; cvta.to.shared.u64 t, %1; cvt.u32.u64 %0, t; }"
        : "=r"(a) : "l"(p));
    return a;
}
__device__ __forceinline__ void cp16(uint32_t d, const void* s) {
    asm volatile("cp.async.cg.shared.global [%0], [%1], 16;\n" :: "r"(d), "l"(s));
}
__device__ __forceinline__ void ldsm_x4(uint32_t* r, uint32_t a) {
    asm volatile("ldmatrix.sync.aligned.m8n8.x4.shared.b16 {%0,%1,%2,%3}, [%4];"
                 : "=r"(r[0]), "=r"(r[1]), "=r"(r[2]), "=r"(r[3]) : "r"(a));
}
__device__ __forceinline__ void mma16816(float* c, const uint32_t* a,
                                         const uint32_t* b) {
    asm volatile(
        "mma.sync.aligned.m16n8k16.row.col.f32.bf16.bf16.f32 "
        "{%0,%1,%2,%3}, {%4,%5,%6,%7}, {%8,%9}, {%0,%1,%2,%3};\n"
        : "+f"(c[0]), "+f"(c[1]), "+f"(c[2]), "+f"(c[3])
        : "r"(a[0]), "r"(a[1]), "r"(a[2]), "r"(a[3]), "r"(b[0]), "r"(b[1]));
}

// Issue loads for global stage g (tile j = g/4, k chunk g%4). Always commits
// a group (possibly empty) so wait_group depth stays uniform.
__device__ __forceinline__ void load_stage(uint32_t sbase, int g,
                                           int ntiles_cta, int bid, int stride,
                                           int tid) {
    int j = g >> 2;
    if (j < ntiles_cta) {
        int T = bid + j * stride;
        int mB = (T & (MTILES - 1)) * TM;
        int nB = (T >> 6) * TN;
        int kk = (g & 3) * BK;
        const char* aS = (const char*)g_xbf + (size_t)mB * (DD * 2) + kk * 2;
        const char* bS = (const char*)g_sbf + (size_t)nB * (DD * 2) + kk * 2;
        int r0 = tid >> 3;       // 0..31
        int jg = tid & 7;        // 16B granule within 128B row
        uint32_t sw = (uint32_t)((jg ^ (r0 & 7)) * 16);
        uint32_t aoff = sbase + r0 * 128 + sw;
        size_t goff = (size_t)r0 * (DD * 2) + jg * 16;
#pragma unroll
        for (int i = 0; i < 8; i++)  // A: 256 rows
            cp16(aoff + i * (32 * 128), aS + goff + (size_t)i * (32 * DD * 2));
        uint32_t boff = sbase + A_STAGE + r0 * 128 + sw;
#pragma unroll
        for (int i = 0; i < 4; i++)  // B: 128 rows
            cp16(boff + i * (32 * 128), bS + goff + (size_t)i * (32 * DD * 2));
    }
    asm volatile("cp.async.commit_group;\n");
}

__global__ void __launch_bounds__(256, 1)
rbf_persist_kernel(float* __restrict__ out) {
    extern __shared__ __align__(128) char dsm[];
    const int tid = threadIdx.x;
    const int lane = tid & 31;
    const int wid = tid >> 5;
    const int warpM = wid & 3;   // 4 warps along M (64 rows)
    const int warpN = wid >> 2;  // 2 warps along N (64 cols)
    const int bid = blockIdx.x;
    const int stride = gridDim.x;
    const int ntiles_cta = (NTILES_TOT - bid + stride - 1) / stride;

    const uint32_t s0 = cvta_s(dsm);
    const int swz = lane & 7;
    const int hi = lane >> 4;
    const uint32_t aRowOff = (uint32_t)(warpM * 64 + (lane & 15)) * 128;
    const uint32_t bRowOff = A_STAGE + (uint32_t)(warpN * 64 + (lane & 15)) * 128;

    float acc[4][8][4];
#pragma unroll
    for (int mt = 0; mt < 4; mt++)
#pragma unroll
        for (int nt = 0; nt < 8; nt++)
#pragma unroll
            for (int k = 0; k < 4; k++) acc[mt][nt][k] = 0.f;

    load_stage(s0, 0, ntiles_cta, bid, stride, tid);
    load_stage(s0 + STAGE, 1, ntiles_cta, bid, stride, tid);

    int g = 0;
    for (int j = 0; j < ntiles_cta; j++) {
        const int T = bid + j * stride;
        const int mB = (T & (MTILES - 1)) * TM;
        const int nB = (T >> 6) * TN;

#pragma unroll
        for (int ks4 = 0; ks4 < 4; ks4++, g++) {
            asm volatile("cp.async.wait_group 1;\n");
            __syncthreads();
            load_stage(s0 + (uint32_t)((g + 2) % 3) * STAGE, g + 2, ntiles_cta,
                       bid, stride, tid);
            const uint32_t sb = s0 + (uint32_t)(g % 3) * STAGE;
#pragma unroll
            for (int ks = 0; ks < 4; ks++) {  // 4 k16 steps per BK=64 stage
                const uint32_t csel = (uint32_t)(((ks * 2 + hi) ^ swz) * 16);
                uint32_t a[4][4], b[4][4];
#pragma unroll
                for (int mt = 0; mt < 4; mt++)
                    ldsm_x4(a[mt], sb + aRowOff + mt * (16 * 128) + csel);
#pragma unroll
                for (int bt = 0; bt < 4; bt++)
                    ldsm_x4(b[bt], sb + bRowOff + bt * (16 * 128) + csel);
#pragma unroll
                for (int mt = 0; mt < 4; mt++)
#pragma unroll
                    for (int bt = 0; bt < 4; bt++) {
                        uint32_t b0[2] = {b[bt][0], b[bt][2]};
                        uint32_t b1[2] = {b[bt][1], b[bt][3]};
                        mma16816(acc[mt][bt * 2 + 0], a[mt], b0);
                        mma16816(acc[mt][bt * 2 + 1], a[mt], b1);
                    }
            }
        }

        // Epilogue for tile j. Touches only registers + global memory, so it
        // overlaps the two in-flight cp.async stages of tile j+1.
        {
            const int g8 = lane >> 2;
            const int t4 = lane & 3;
            const int colBase = nB + warpN * 64 + t4 * 2;
            float ssv0[8], ssv1[8];
#pragma unroll
            for (int nt = 0; nt < 8; nt++) {
                ssv0[nt] = g_ssq[colBase + nt * 8];
                ssv1[nt] = g_ssq[colBase + nt * 8 + 1];
            }
#pragma unroll
            for (int mt = 0; mt < 4; mt++) {
                const int r0 = mB + warpM * 64 + mt * 16 + g8;
                const float xs0 = g_xsq[r0];
                const float xs1 = g_xsq[r0 + 8];
                float* o0 = out + (size_t)r0 * NS + colBase;
                float* o1 = o0 + (size_t)8 * NS;
#pragma unroll
                for (int nt = 0; nt < 8; nt++) {
                    float* a4 = acc[mt][nt];
                    float2 v0, v1;
                    v0.x = __expf(-fmaxf(fmaf(-2.f, a4[0], xs0 + ssv0[nt]), 0.f));
                    v0.y = __expf(-fmaxf(fmaf(-2.f, a4[1], xs0 + ssv1[nt]), 0.f));
                    v1.x = __expf(-fmaxf(fmaf(-2.f, a4[2], xs1 + ssv0[nt]), 0.f));
                    v1.y = __expf(-fmaxf(fmaf(-2.f, a4[3], xs1 + ssv1[nt]), 0.f));
                    *reinterpret_cast<float2*>(o0 + nt * 8) = v0;
                    *reinterpret_cast<float2*>(o1 + nt * 8) = v1;
                    a4[0] = 0.f; a4[1] = 0.f; a4[2] = 0.f; a4[3] = 0.f;
                }
            }
        }
    }
}

// ---------------------------------------------------------------------------
extern "C" void kernel_launch(void* const* d_in, const int* in_sizes, int n_in,
                              void* d_out, int out_size) {
    const float* x = (const float*)d_in[0];
    const float* s = (const float*)d_in[1];
    if (n_in >= 2 && in_sizes[0] < in_sizes[1]) {
        x = (const float*)d_in[1];
        s = (const float*)d_in[0];
    }
    float* out = (float*)d_out;

    static int nsm = 0;
    if (nsm == 0) {
        cudaFuncSetAttribute(rbf_persist_kernel,
                             cudaFuncAttributeMaxDynamicSharedMemorySize,
                             DYN_SMEM);
        cudaDeviceGetAttribute(&nsm, cudaDevAttrMultiProcessorCount, 0);
        if (nsm <= 0) nsm = 148;
    }

    prep_kernel<<<(NX + NS) / 8, 256>>>(x, s);
    rbf_persist_kernel<<<nsm, 256, DYN_SMEM>>>(out);
}

// round 5
// speedup vs baseline: 1.1815x; 1.1815x over previous
#include <cuda_runtime.h>
#include <cuda_fp16.h>
#include <cstdint>

#define NX 16384
#define NS 4096
#define DD 256

#define TM 256              // CTA tile M
#define TN 128              // CTA tile N
#define MTILES (NX / TM)    // 64
#define NTILES_TOT ((NX / TM) * (NS / TN))  // 2048
#define BK 64               // K per stage (64 f16 = 128B rows)
#define A_STAGE (TM * 128)  // 32 KB
#define B_STAGE (TN * 128)  // 16 KB
#define STAGE (A_STAGE + B_STAGE)  // 48 KB
#define DYN_SMEM (2 * STAGE)       // 98304 -> 2 CTAs/SM

#define L2E 1.4426950408889634f
#define C2L2E 2.8853900817779268f  // 2*log2(e)

// Scratch (device globals; no allocation allowed)
__device__ __align__(16) __half g_xh[NX * DD];
__device__ __align__(16) __half g_sh[NS * DD];
__device__ float g_xls[NX];  // -||x||^2 * log2(e)
__device__ float g_sls[NS];  // -||s||^2 * log2(e)

// ---------------------------------------------------------------------------
// Prep: fp32 -> fp16 + pre-scaled row norms. One warp per row.
// ---------------------------------------------------------------------------
__global__ void prep_kernel(const float* __restrict__ x,
                            const float* __restrict__ s) {
    int warp = (blockIdx.x * blockDim.x + threadIdx.x) >> 5;
    int lane = threadIdx.x & 31;
    if (warp >= NX + NS) return;
    const float* src;
    __half* dst;
    float* sqout;
    if (warp < NX) {
        src = x + (size_t)warp * DD; dst = g_xh + (size_t)warp * DD; sqout = g_xls + warp;
    } else {
        int r = warp - NX;
        src = s + (size_t)r * DD; dst = g_sh + (size_t)r * DD; sqout = g_sls + r;
    }
    float4 v0 = reinterpret_cast<const float4*>(src)[lane * 2];
    float4 v1 = reinterpret_cast<const float4*>(src)[lane * 2 + 1];
    __half2 p0 = __floats2half2_rn(v0.x, v0.y);
    __half2 p1 = __floats2half2_rn(v0.z, v0.w);
    __half2 p2 = __floats2half2_rn(v1.x, v1.y);
    __half2 p3 = __floats2half2_rn(v1.z, v1.w);
    uint4 pk;
    pk.x = *reinterpret_cast<uint32_t*>(&p0);
    pk.y = *reinterpret_cast<uint32_t*>(&p1);
    pk.z = *reinterpret_cast<uint32_t*>(&p2);
    pk.w = *reinterpret_cast<uint32_t*>(&p3);
    reinterpret_cast<uint4*>(dst)[lane] = pk;
    float p = v0.x * v0.x + v0.y * v0.y + v0.z * v0.z + v0.w * v0.w +
              v1.x * v1.x + v1.y * v1.y + v1.z * v1.z + v1.w * v1.w;
#pragma unroll
    for (int o = 16; o; o >>= 1) p += __shfl_xor_sync(0xffffffffu, p, o);
    if (lane == 0) *sqout = -p * L2E;
}

// ---------------------------------------------------------------------------
__device__ __forceinline__ uint32_t cvta_s(const void* p) {
    uint32_t a;
    asm("{ .reg .u64 t; cvta.to.shared.u64 t, %1; cvt.u32.u64 %0, t; }"
        : "=r"(a) : "l"(p));
    return a;
}
__device__ __forceinline__ void cp16(uint32_t d, const void* s) {
    asm volatile("cp.async.cg.shared.global [%0], [%1], 16;\n" :: "r"(d), "l"(s));
}
__device__ __forceinline__ void ldsm_x4(uint32_t* r, uint32_t a) {
    asm volatile("ldmatrix.sync.aligned.m8n8.x4.shared.b16 {%0,%1,%2,%3}, [%4];"
                 : "=r"(r[0]), "=r"(r[1]), "=r"(r[2]), "=r"(r[3]) : "r"(a));
}
// f16-accumulate HMMA
__device__ __forceinline__ void mma_f16(uint32_t* c, const uint32_t* a,
                                        uint32_t b0, uint32_t b1) {
    asm volatile(
        "mma.sync.aligned.m16n8k16.row.col.f16.f16.f16.f16 "
        "{%0,%1}, {%2,%3,%4,%5}, {%6,%7}, {%0,%1};\n"
        : "+r"(c[0]), "+r"(c[1])
        : "r"(a[0]), "r"(a[1]), "r"(a[2]), "r"(a[3]), "r"(b0), "r"(b1));
}
__device__ __forceinline__ float ex2(float w) {
    float r;
    asm("ex2.approx.f32 %0, %1;" : "=f"(r) : "f"(w));
    return r;
}

// B row permutation: smem row nb for global col gc (0..127) so that thread t4
// of n-tile pair (2k,2k+1) owns 4 consecutive global cols 16k+4*t4+{0..3}.
__device__ __forceinline__ int bperm(int gc) {
    int k = gc >> 4, w = gc & 15;
    int t4 = w >> 2, r = w & 3;
    return 16 * k + 8 * (r >> 1) + 2 * t4 + (r & 1);
}

// Load stage for global chunk g (tile j = g/4, k-chunk g%4). Always commits.
__device__ __forceinline__ void load_stage(uint32_t sbase, int g,
                                           int ntiles_cta, int bid, int stride,
                                           int tid) {
    int j = g >> 2;
    if (j < ntiles_cta) {
        int T = bid + j * stride;
        int mB = (T & (MTILES - 1)) * TM;
        int nB = (T >> 6) * TN;
        int kb = (g & 3) * 128;  // byte offset of K-chunk within 512B row
        const char* aS = (const char*)g_xh + (size_t)mB * 512 + kb;
        const char* bS = (const char*)g_sh + (size_t)nB * 512 + kb;
        int r0 = tid >> 3;       // 0..31
        int jg = tid & 7;        // 16B granule within 128B row
        size_t goff = (size_t)r0 * 512 + jg * 16;
        uint32_t aoff = sbase + r0 * 128 + (uint32_t)((jg ^ (r0 & 7)) * 16);
#pragma unroll
        for (int i = 0; i < 8; i++)  // A: 256 rows
            cp16(aoff + i * (32 * 128), aS + goff + (size_t)i * (32 * 512));
#pragma unroll
        for (int i = 0; i < 4; i++) {  // B: 128 rows, permuted destination
            int gc = r0 + 32 * i;
            int nb = bperm(gc);
            uint32_t boff =
                sbase + A_STAGE + nb * 128 + (uint32_t)((jg ^ (nb & 7)) * 16);
            cp16(boff, bS + (size_t)gc * 512 + jg * 16);
        }
    }
    asm volatile("cp.async.commit_group;\n");
}

__global__ void __launch_bounds__(256, 2)
rbf_f16_kernel(float* __restrict__ out) {
    extern __shared__ __align__(128) char dsm[];
    const int tid = threadIdx.x;
    const int lane = tid & 31;
    const int wid = tid >> 5;
    const int warpM = wid & 3;   // 4 warps along M (64 rows each)
    const int warpN = wid >> 2;  // 2 warps along N (64 cols each)
    const int bid = blockIdx.x;
    const int stride = gridDim.x;
    const int ntiles_cta = (NTILES_TOT - bid + stride - 1) / stride;
    if (ntiles_cta <= 0) return;

    const uint32_t s0 = cvta_s(dsm);
    const int swz = lane & 7;
    const int hi = lane >> 4;
    const uint32_t aRowOff = (uint32_t)(warpM * 64 + (lane & 15)) * 128;
    const uint32_t bRowOff =
        A_STAGE + (uint32_t)(warpN * 64 + (lane & 15)) * 128;

    uint32_t acc[4][8][2];
#pragma unroll
    for (int mt = 0; mt < 4; mt++)
#pragma unroll
        for (int nt = 0; nt < 8; nt++) {
            acc[mt][nt][0] = 0u; acc[mt][nt][1] = 0u;
        }

    load_stage(s0, 0, ntiles_cta, bid, stride, tid);
    load_stage(s0 + STAGE, 1, ntiles_cta, bid, stride, tid);

    int g = 0;
    for (int j = 0; j < ntiles_cta; j++) {
        const int T = bid + j * stride;
        const int mB = (T & (MTILES - 1)) * TM;
        const int nB = (T >> 6) * TN;

#pragma unroll
        for (int c4 = 0; c4 < 4; c4++, g++) {
            asm volatile("cp.async.wait_group 1;\n");
            __syncthreads();
            const uint32_t sb = s0 + (uint32_t)(g & 1) * STAGE;
#pragma unroll
            for (int ks = 0; ks < 4; ks++) {
                const uint32_t csel = (uint32_t)(((ks * 2 + hi) ^ swz) * 16);
                uint32_t a[4][4];
#pragma unroll
                for (int mt = 0; mt < 4; mt++)
                    ldsm_x4(a[mt], sb + aRowOff + mt * (16 * 128) + csel);
#pragma unroll
                for (int bt = 0; bt < 4; bt++) {
                    uint32_t bb[4];
                    ldsm_x4(bb, sb + bRowOff + bt * (16 * 128) + csel);
#pragma unroll
                    for (int mt = 0; mt < 4; mt++) {
                        mma_f16(acc[mt][bt * 2 + 0], a[mt], bb[0], bb[2]);
                        mma_f16(acc[mt][bt * 2 + 1], a[mt], bb[1], bb[3]);
                    }
                }
            }
            __syncthreads();  // all warps done with buffer g&1
            load_stage(s0 + (uint32_t)(g & 1) * STAGE, g + 2, ntiles_cta, bid,
                       stride, tid);
        }

        // Epilogue: out = min(2^(log2e*(2*dot - xs - ss)), 1). Registers +
        // global only, overlapping the in-flight cp.async of the next tile.
        {
            const int g8 = lane >> 2;
            const int t4 = lane & 3;
            const int colF = nB + warpN * 64 + t4 * 4;
            float4 ss4[4];
#pragma unroll
            for (int k = 0; k < 4; k++)
                ss4[k] = *reinterpret_cast<const float4*>(g_sls + colF + 16 * k);
#pragma unroll
            for (int mt = 0; mt < 4; mt++) {
                const int r0 = mB + warpM * 64 + mt * 16 + g8;
                const float xsl0 = g_xls[r0];
                const float xsl1 = g_xls[r0 + 8];
                float* o0 = out + (size_t)r0 * NS + colF;
                float* o1 = o0 + (size_t)8 * NS;
#pragma unroll
                for (int k = 0; k < 4; k++) {
                    uint32_t* e0 = acc[mt][2 * k];
                    uint32_t* e1 = acc[mt][2 * k + 1];
                    float2 fa = __half22float2(*(const __half2*)&e0[0]);
                    float2 fb = __half22float2(*(const __half2*)&e1[0]);
                    float2 fc = __half22float2(*(const __half2*)&e0[1]);
                    float2 fd = __half22float2(*(const __half2*)&e1[1]);
                    float4 v0, v1;
                    v0.x = fminf(ex2(fmaf(fa.x, C2L2E, xsl0 + ss4[k].x)), 1.f);
                    v0.y = fminf(ex2(fmaf(fa.y, C2L2E, xsl0 + ss4[k].y)), 1.f);
                    v0.z = fminf(ex2(fmaf(fb.x, C2L2E, xsl0 + ss4[k].z)), 1.f);
                    v0.w = fminf(ex2(fmaf(fb.y, C2L2E, xsl0 + ss4[k].w)), 1.f);
                    v1.x = fminf(ex2(fmaf(fc.x, C2L2E, xsl1 + ss4[k].x)), 1.f);
                    v1.y = fminf(ex2(fmaf(fc.y, C2L2E, xsl1 + ss4[k].y)), 1.f);
                    v1.z = fminf(ex2(fmaf(fd.x, C2L2E, xsl1 + ss4[k].z)), 1.f);
                    v1.w = fminf(ex2(fmaf(fd.y, C2L2E, xsl1 + ss4[k].w)), 1.f);
                    *reinterpret_cast<float4*>(o0 + 16 * k) = v0;
                    *reinterpret_cast<float4*>(o1 + 16 * k) = v1;
                    e0[0] = 0u; e0[1] = 0u; e1[0] = 0u; e1[1] = 0u;
                }
            }
        }
    }
}

// ---------------------------------------------------------------------------
extern "C" void kernel_launch(void* const* d_in, const int* in_sizes, int n_in,
                              void* d_out, int out_size) {
    const float* x = (const float*)d_in[0];
    const float* s = (const float*)d_in[1];
    if (n_in >= 2 && in_sizes[0] < in_sizes[1]) {
        x = (const float*)d_in[1];
        s = (const float*)d_in[0];
    }
    float* out = (float*)d_out;

    static int nsm = 0;
    if (nsm == 0) {
        cudaFuncSetAttribute(rbf_f16_kernel,
                             cudaFuncAttributeMaxDynamicSharedMemorySize,
                             DYN_SMEM);
        cudaDeviceGetAttribute(&nsm, cudaDevAttrMultiProcessorCount, 0);
        if (nsm <= 0) nsm = 148;
    }

    prep_kernel<<<(NX + NS) / 8, 256>>>(x, s);
    rbf_f16_kernel<<<2 * nsm, 256, DYN_SMEM>>>(out);
}